// round 16
// baseline (speedup 1.0000x reference)
#include <cuda_runtime.h>
#include <cstdint>

#define VOCAB 128
#define NTAGS 8
#define EDIM  256
#define HDIM  1024
#define BATCH 1024
#define SEQ   128

// ------------------------- device scratch (static, no allocs) -------------
__device__ float    g_Q[VOCAB * HDIM];                    // 512 KB, L2-resident
__device__ int      g_len[BATCH];
__device__ float    g_H[(size_t)SEQ * BATCH * HDIM];      // 512 MB: h after step t
__device__ unsigned g_flag[8][16 * 32];                   // per-CTA step flags (128B apart)

// ===========================================================================
// Q[v][h] = sum_e emb[v][e] * W_ih[h][e] + b_ih[h] + b_hh[h]
// ===========================================================================
__global__ void q_kernel(const float* __restrict__ emb,
                         const float* __restrict__ W_ih,
                         const float* __restrict__ b_ih,
                         const float* __restrict__ b_hh) {
    int v = blockIdx.x;
    int warp = threadIdx.x >> 5, lane = threadIdx.x & 31;
    const float* e = emb + v * EDIM;
    for (int h = warp; h < HDIM; h += 8) {
        const float* w = W_ih + h * EDIM;
        float acc = 0.f;
        #pragma unroll
        for (int k = lane; k < EDIM; k += 32) acc += e[k] * w[k];
        #pragma unroll
        for (int o = 16; o > 0; o >>= 1) acc += __shfl_down_sync(0xffffffffu, acc, o);
        if (lane == 0) g_Q[v * HDIM + h] = acc + b_ih[h] + b_hh[h];
    }
}

// ===========================================================================
// seq_lengths + t=0 step (h0 = 0) + reset producer flags
// ===========================================================================
__global__ void t0_kernel(const int* __restrict__ ids) {
    int b = blockIdx.x, tid = threadIdx.x;
    if (b < 8 && tid < 16) g_flag[b][tid * 32] = 0u;   // reset flags each replay

    int m = (ids[b * SEQ + tid] != 0) ? 1 : 0;
    __shared__ int ws[4];
    #pragma unroll
    for (int o = 16; o > 0; o >>= 1) m += __shfl_down_sync(0xffffffffu, m, o);
    if ((tid & 31) == 0) ws[tid >> 5] = m;
    __syncthreads();
    int len = ws[0] + ws[1] + ws[2] + ws[3];
    if (tid == 0) g_len[b] = len;

    int id0 = ids[b * SEQ];
    const float* q = g_Q + (size_t)id0 * HDIM;
    float* hout = g_H + (size_t)b * HDIM;
    for (int h = tid; h < HDIM; h += 128)
        hout[h] = (len > 0) ? tanhf(q[h]) : 0.f;
}

// ======================== shared GEMM helpers ==============================
__device__ __forceinline__ void cp16(float* sp, const float* gp) {
    uint32_t s = (uint32_t)__cvta_generic_to_shared(sp);
    asm volatile("cp.async.cg.shared.global [%0], [%1], 16;\n" :: "r"(s), "l"(gp));
}

__device__ __forceinline__ void mma_tf32(float* d, const uint32_t* a, const uint32_t* b) {
    asm volatile(
        "mma.sync.aligned.m16n8k8.row.col.f32.tf32.tf32.f32 "
        "{%0,%1,%2,%3}, {%4,%5,%6,%7}, {%8,%9}, {%0,%1,%2,%3};\n"
        : "+f"(d[0]), "+f"(d[1]), "+f"(d[2]), "+f"(d[3])
        : "r"(a[0]), "r"(a[1]), "r"(a[2]), "r"(a[3]), "r"(b[0]), "r"(b[1]));
}

// hi/lo tf32 split: x ≈ hi + lo with err ~2^-24 (fp32-equivalent via 3 MMAs)
__device__ __forceinline__ void split_tf32(float x, uint32_t& hi, uint32_t& lo) {
    asm("cvt.rna.tf32.f32 %0, %1;" : "=r"(hi) : "f"(x));
    float l = x - __uint_as_float(hi);
    asm("cvt.rna.tf32.f32 %0, %1;" : "=r"(lo) : "f"(l));
}

extern __shared__ float smem_dyn[];

// ===========================================================================
// rnn_kernel: PERSISTENT — one launch runs all 127 steps.
// EXACT R12 GEMM shape: 128 CTAs (1/SM), 256 threads, CTA tile 128x64,
// warp tile 32x32, NST=3 stages, KCH=64, 16 chunks, lookahead 2.
// NEW: monolithic 16-CTA step barrier replaced by per-producer dataflow
// flags. Chunk j of H[t-1] (columns [64j,64j+64)) is produced by CTA
// (grp, sub=j); the consumer gates chunk j's cp.async issue on
// g_flag[grp][j] >= t-1, checked by tid0 between wait_group and the
// existing per-chunk __syncthreads (no extra barriers). Refill for
// chunk ch+2 is issued right after the top-of-chunk barrier so the gate
// covers it. Producer publishes flag=t after its fenced epilogue.
// ===========================================================================
#define KCH        64
#define NCHK       (HDIM / KCH)            /* 16 */
#define PITCH      68                      /* 68 ≡ 4 (mod 32): conflict-free */
#define A_F        (128 * PITCH)           /* 8704 floats */
#define B_F        (64  * PITCH)           /* 4352 floats */
#define STAGE_F    (A_F + B_F)             /* 13056 floats = 52224 B */
#define NST        3
#define RNN_SMEM   (NST * STAGE_F * 4)     /* 156672 B */

__global__ void __launch_bounds__(256, 1)
rnn_kernel(const float* __restrict__ W_hh, const int* __restrict__ ids) {
    const int tid  = threadIdx.x;
    const int lane = tid & 31, warp = tid >> 5;
    const int wm = warp & 3, wn = warp >> 2;       // 4x2 warps, each 32x32
    const int g  = lane >> 2, c = lane & 3;
    const int grp = blockIdx.x >> 4;
    const int sub = blockIdx.x & 15;
    const int m0 = grp * 128;
    const int n0 = sub * 64;

    // tid0-only: spin until producer of chunk j reached step tgt (release
    // by producer's __threadfence + atomicExch; __syncthreads after this
    // call broadcasts the acquired visibility to all threads).
    #define WAIT_FLAG(j, tgt)                                                      \
        do {                                                                       \
            if (tid == 0) {                                                        \
                volatile unsigned* f_ = &g_flag[grp][(j) * 32];                    \
                while (*f_ < (unsigned)(tgt)) __nanosleep(32);                     \
                __threadfence();                                                   \
            }                                                                      \
        } while (0)

    #define LOAD_A(st, k0, Hp)                                                     \
        do {                                                                       \
            float* base = smem_dyn + (st) * STAGE_F;                               \
            _Pragma("unroll")                                                      \
            for (int i = 0; i < 8; i++) {                                          \
                int j = tid + i * 256;                                             \
                int r = j >> 4, c16 = j & 15;                                      \
                cp16(base + r * PITCH + c16 * 4,                                   \
                     (Hp) + (size_t)(m0 + r) * HDIM + (k0) + c16 * 4);             \
            }                                                                      \
        } while (0)
    #define LOAD_B(st, k0)                                                         \
        do {                                                                       \
            float* base = smem_dyn + (st) * STAGE_F + A_F;                         \
            _Pragma("unroll")                                                      \
            for (int i = 0; i < 4; i++) {                                          \
                int j = tid + i * 256;                                             \
                int r = j >> 4, c16 = j & 15;                                      \
                cp16(base + r * PITCH + c16 * 4,                                   \
                     W_hh + (size_t)(n0 + r) * HDIM + (k0) + c16 * 4);             \
            }                                                                      \
        } while (0)

    #define LDFRAG(da, db, ksv)                                                    \
        do {                                                                       \
            _Pragma("unroll")                                                      \
            for (int mt = 0; mt < 2; mt++) {                                       \
                const float* ap = A + (mt * 16 + g) * PITCH + (ksv) * 8 + c;       \
                da[mt][0] = __float_as_uint(ap[0]);                                \
                da[mt][1] = __float_as_uint(ap[8 * PITCH]);                        \
                da[mt][2] = __float_as_uint(ap[4]);                                \
                da[mt][3] = __float_as_uint(ap[8 * PITCH + 4]);                    \
            }                                                                      \
            _Pragma("unroll")                                                      \
            for (int nt = 0; nt < 4; nt++) {                                       \
                const float* bp = B + (nt * 8 + g) * PITCH + (ksv) * 8 + c;        \
                db[nt][0] = __float_as_uint(bp[0]);                                \
                db[nt][1] = __float_as_uint(bp[4]);                                \
            }                                                                      \
        } while (0)

    // W for stages 0/1 of the first step (uncommitted; joins first commit)
    LOAD_B(0, 0);
    LOAD_B(1, KCH);

    for (int t = 1; t < SEQ; t++) {
        const float* __restrict__ Hprev = g_H + (size_t)(t - 1) * BATCH * HDIM;
        float* __restrict__ Hout        = g_H + (size_t)t       * BATCH * HDIM;

        float acc[2][4][4] = {};

        // ---- prologue gate: chunks 0/1 of Hprev (producers sub=0, sub=1) ---
        WAIT_FLAG(0, t - 1);
        WAIT_FLAG(1, t - 1);
        __syncthreads();

        LOAD_A(0, 0, Hprev);
        asm volatile("cp.async.commit_group;\n");   // G0 = {B0, B1, A0}
        LOAD_A(1, KCH, Hprev);
        asm volatile("cp.async.commit_group;\n");   // G1 = {A1}

        for (int ch = 0; ch < NCHK; ch++) {
            if (ch < NCHK - 1) asm volatile("cp.async.wait_group 1;\n");
            else               asm volatile("cp.async.wait_group 0;\n");

            // gate the refill issued just after this barrier
            if (ch + 2 < NCHK) WAIT_FLAG(ch + 2, t - 1);
            __syncthreads();

            // refill chunk ch+2 into stage (ch+2)%3 (last read at chunk ch-1;
            // the barrier above ordered all warps past it)
            if (ch + 2 < NCHK) {
                const int st2 = (ch + 2) % NST;
                LOAD_A(st2, (ch + 2) * KCH, Hprev);
                LOAD_B(st2, (ch + 2) * KCH);
                asm volatile("cp.async.commit_group;\n");
            }

            const int st = ch % NST;
            const float* A = smem_dyn + st * STAGE_F + (wm * 32) * PITCH;
            const float* B = smem_dyn + st * STAGE_F + A_F + (wn * 32) * PITCH;

            uint32_t af[2][2][4], bf[2][4][2];
            LDFRAG(af[0], bf[0], 0);
            #pragma unroll
            for (int ks = 0; ks < KCH / 8; ks++) {
                const int cur = ks & 1;
                if (ks < KCH / 8 - 1) LDFRAG(af[cur ^ 1], bf[cur ^ 1], ks + 1);
                #pragma unroll
                for (int mt = 0; mt < 2; mt++)
                    #pragma unroll
                    for (int nt = 0; nt < 4; nt++)
                        mma_tf32(acc[mt][nt], af[cur][mt], bf[cur][nt]);
            }
        }

        // all warps past chunk 15 compute before overwriting stage 0/1 B
        __syncthreads();
        if (t + 1 < SEQ) {        // next step's W prefetch (step-invariant)
            LOAD_B(0, 0);
            LOAD_B(1, KCH);
        }

        // ---- epilogue: + Q gather, tanh, mask ------------------------------
        const int c2 = c * 2;
        #pragma unroll
        for (int mt = 0; mt < 2; mt++) {
            const int rA = m0 + wm * 32 + mt * 16 + g;
            const int rB = rA + 8;
            const int idA = ids[rA * SEQ + t];
            const int idB = ids[rB * SEQ + t];
            const bool mA = t < g_len[rA];
            const bool mB = t < g_len[rB];
            const float* q0 = g_Q + (size_t)idA * HDIM;
            const float* q1 = g_Q + (size_t)idB * HDIM;
            float* o0 = Hout + (size_t)rA * HDIM;
            float* o1 = Hout + (size_t)rB * HDIM;
            const float* p0 = Hprev + (size_t)rA * HDIM;
            const float* p1 = Hprev + (size_t)rB * HDIM;
            #pragma unroll
            for (int nt = 0; nt < 4; nt++) {
                const int n = n0 + wn * 32 + nt * 8 + c2;
                o0[n]     = mA ? tanhf(acc[mt][nt][0] + q0[n])     : p0[n];
                o0[n + 1] = mA ? tanhf(acc[mt][nt][1] + q0[n + 1]) : p0[n + 1];
                o1[n]     = mB ? tanhf(acc[mt][nt][2] + q1[n])     : p1[n];
                o1[n + 1] = mB ? tanhf(acc[mt][nt][3] + q1[n + 1]) : p1[n + 1];
            }
        }

        if (t + 1 >= SEQ) break;

        // ---- publish: this CTA's H[t] column slice is complete --------------
        __syncthreads();                          // all epilogue stores issued
        if (tid == 0) {
            __threadfence();                      // release to device scope
            atomicExch(&g_flag[grp][sub * 32], (unsigned)t);
        }
    }
    #undef LOAD_A
    #undef LOAD_B
    #undef LDFRAG
    #undef WAIT_FLAG
}

// ===========================================================================
// y_kernel v3 (unchanged R12): tensor-core GEMM, hi/lo tf32 split.
// ===========================================================================
#define YKCH      64
#define YNCHK     (HDIM / YKCH)             /* 16 */
#define YPITCH    68
#define YA_F      (128 * YPITCH)            /* 8704 floats */
#define YB_F      (8   * YPITCH)            /* 544 floats */
#define YSTAGE_F  (YA_F + YB_F)             /* 9248 floats = 36992 B */
#define YNST      3
#define Y_SMEM    (YNST * YSTAGE_F * 4)     /* 110976 B */

__global__ void __launch_bounds__(128, 1)
y_kernel(const float* __restrict__ W_out,
         const float* __restrict__ b_out,
         float* __restrict__ y) {
    const int tid  = threadIdx.x;
    const int lane = tid & 31, warp = tid >> 5;
    const int g = lane >> 2, c = lane & 3;
    const int m0 = blockIdx.x * 128;        // row block (r = t*BATCH + b)

    #define YLOAD(st, k0)                                                          \
        do {                                                                       \
            float* base = smem_dyn + (st) * YSTAGE_F;                              \
            _Pragma("unroll")                                                      \
            for (int i = 0; i < 16; i++) {                                         \
                int j = tid + i * 128;                                             \
                int r = j >> 4, c16 = j & 15;                                      \
                cp16(base + r * YPITCH + c16 * 4,                                  \
                     g_H + (size_t)(m0 + r) * HDIM + (k0) + c16 * 4);              \
            }                                                                      \
            {                                                                      \
                int r = tid >> 4, c16 = tid & 15;                                  \
                cp16(base + YA_F + r * YPITCH + c16 * 4,                           \
                     W_out + (size_t)r * HDIM + (k0) + c16 * 4);                   \
            }                                                                      \
            asm volatile("cp.async.commit_group;\n");                              \
        } while (0)

    float acc[2][4] = {};

    YLOAD(0, 0);
    YLOAD(1, YKCH);

    for (int ch = 0; ch < YNCHK; ch++) {
        if (ch < YNCHK - 1) asm volatile("cp.async.wait_group 1;\n");
        else                asm volatile("cp.async.wait_group 0;\n");
        __syncthreads();

        const int st = ch % YNST;
        const float* A = smem_dyn + st * YSTAGE_F + (warp * 32) * YPITCH;
        const float* B = smem_dyn + st * YSTAGE_F + YA_F;

        #pragma unroll
        for (int ks = 0; ks < YKCH / 8; ks++) {
            uint32_t bh[2], bl[2];
            {
                const float* bp = B + g * YPITCH + ks * 8 + c;
                split_tf32(bp[0], bh[0], bl[0]);
                split_tf32(bp[4], bh[1], bl[1]);
            }
            #pragma unroll
            for (int mt = 0; mt < 2; mt++) {
                const float* ap = A + (mt * 16 + g) * YPITCH + ks * 8 + c;
                uint32_t ah[4], al[4];
                split_tf32(ap[0],            ah[0], al[0]);
                split_tf32(ap[8 * YPITCH],   ah[1], al[1]);
                split_tf32(ap[4],            ah[2], al[2]);
                split_tf32(ap[8 * YPITCH+4], ah[3], al[3]);
                mma_tf32(acc[mt], ah, bh);    // hi*hi
                mma_tf32(acc[mt], al, bh);    // lo*hi
                mma_tf32(acc[mt], ah, bl);    // hi*lo
            }
        }

        if (ch + 2 < YNCHK) YLOAD((ch + 2) % YNST, (ch + 2) * YKCH);
    }

    const int n0t = 2 * c;                          // tags 2c, 2c+1
    const float bo0 = b_out[n0t], bo1 = b_out[n0t + 1];
    #pragma unroll
    for (int mt = 0; mt < 2; mt++) {
        const int rA = m0 + warp * 32 + mt * 16 + g;
        const int rB = rA + 8;
        const int tA = rA >> 10, bA = rA & 1023;    // r = t*BATCH + b
        const int tB = rB >> 10, bB = rB & 1023;
        float2 vA = make_float2(acc[mt][0] + bo0, acc[mt][1] + bo1);
        float2 vB = make_float2(acc[mt][2] + bo0, acc[mt][3] + bo1);
        *(float2*)(y + ((size_t)bA * SEQ + tA) * NTAGS + n0t) = vA;
        *(float2*)(y + ((size_t)bB * SEQ + tB) * NTAGS + n0t) = vB;
    }
    #undef YLOAD
}

// ===========================================================================
extern "C" void kernel_launch(void* const* d_in, const int* in_sizes, int n_in,
                              void* d_out, int out_size) {
    (void)in_sizes; (void)n_in; (void)out_size;
    const int*   ids   = (const int*)  d_in[0];
    const float* emb   = (const float*)d_in[1];
    const float* W_ih  = (const float*)d_in[2];
    const float* W_hh  = (const float*)d_in[3];
    const float* b_ih  = (const float*)d_in[4];
    const float* b_hh  = (const float*)d_in[5];
    const float* W_out = (const float*)d_in[6];
    const float* b_out = (const float*)d_in[7];
    float* y = (float*)d_out;

    cudaFuncSetAttribute(rnn_kernel,
                         cudaFuncAttributeMaxDynamicSharedMemorySize, RNN_SMEM);
    cudaFuncSetAttribute(y_kernel,
                         cudaFuncAttributeMaxDynamicSharedMemorySize, Y_SMEM);

    q_kernel<<<VOCAB, 256>>>(emb, W_ih, b_ih, b_hh);
    t0_kernel<<<BATCH, 128>>>(ids);
    rnn_kernel<<<128, 256, RNN_SMEM>>>(W_hh, ids);   // persistent: all 127 steps
    y_kernel<<<(BATCH * SEQ) / 128, 128, Y_SMEM>>>(W_out, b_out, y);
}

// round 17
// speedup vs baseline: 1.5024x; 1.5024x over previous
#include <cuda_runtime.h>
#include <cstdint>

#define VOCAB 128
#define NTAGS 8
#define EDIM  256
#define HDIM  1024
#define BATCH 1024
#define SEQ   128

// ------------------------- device scratch (static, no allocs) -------------
__device__ float    g_Q[VOCAB * HDIM];                    // 512 KB, L2-resident
__device__ int      g_len[BATCH];
__device__ float    g_H[(size_t)SEQ * BATCH * HDIM];      // 512 MB: h after step t
__device__ unsigned g_bar[8];                             // per-group step counters

// ===========================================================================
// Q[v][h] = sum_e emb[v][e] * W_ih[h][e] + b_ih[h] + b_hh[h]
// ===========================================================================
__global__ void q_kernel(const float* __restrict__ emb,
                         const float* __restrict__ W_ih,
                         const float* __restrict__ b_ih,
                         const float* __restrict__ b_hh) {
    int v = blockIdx.x;
    int warp = threadIdx.x >> 5, lane = threadIdx.x & 31;
    const float* e = emb + v * EDIM;
    for (int h = warp; h < HDIM; h += 8) {
        const float* w = W_ih + h * EDIM;
        float acc = 0.f;
        #pragma unroll
        for (int k = lane; k < EDIM; k += 32) acc += e[k] * w[k];
        #pragma unroll
        for (int o = 16; o > 0; o >>= 1) acc += __shfl_down_sync(0xffffffffu, acc, o);
        if (lane == 0) g_Q[v * HDIM + h] = acc + b_ih[h] + b_hh[h];
    }
}

// ===========================================================================
// seq_lengths + t=0 step (h0 = 0) + reset group barriers
// ===========================================================================
__global__ void t0_kernel(const int* __restrict__ ids) {
    int b = blockIdx.x, tid = threadIdx.x;
    if (b < 8 && tid == 0) g_bar[b] = 0u;   // reset persistent-kernel barriers

    int m = (ids[b * SEQ + tid] != 0) ? 1 : 0;
    __shared__ int ws[4];
    #pragma unroll
    for (int o = 16; o > 0; o >>= 1) m += __shfl_down_sync(0xffffffffu, m, o);
    if ((tid & 31) == 0) ws[tid >> 5] = m;
    __syncthreads();
    int len = ws[0] + ws[1] + ws[2] + ws[3];
    if (tid == 0) g_len[b] = len;

    int id0 = ids[b * SEQ];
    const float* q = g_Q + (size_t)id0 * HDIM;
    float* hout = g_H + (size_t)b * HDIM;
    for (int h = tid; h < HDIM; h += 128)
        hout[h] = (len > 0) ? tanhf(q[h]) : 0.f;
}

// ======================== shared GEMM helpers ==============================
__device__ __forceinline__ void cp16(float* sp, const float* gp) {
    uint32_t s = (uint32_t)__cvta_generic_to_shared(sp);
    asm volatile("cp.async.cg.shared.global [%0], [%1], 16;\n" :: "r"(s), "l"(gp));
}

__device__ __forceinline__ void mma_tf32(float* d, const uint32_t* a, const uint32_t* b) {
    asm volatile(
        "mma.sync.aligned.m16n8k8.row.col.f32.tf32.tf32.f32 "
        "{%0,%1,%2,%3}, {%4,%5,%6,%7}, {%8,%9}, {%0,%1,%2,%3};\n"
        : "+f"(d[0]), "+f"(d[1]), "+f"(d[2]), "+f"(d[3])
        : "r"(a[0]), "r"(a[1]), "r"(a[2]), "r"(a[3]), "r"(b[0]), "r"(b[1]));
}

// hi/lo tf32 split: x ≈ hi + lo with err ~2^-24 (fp32-equivalent via 3 MMAs)
__device__ __forceinline__ void split_tf32(float x, uint32_t& hi, uint32_t& lo) {
    asm("cvt.rna.tf32.f32 %0, %1;" : "=r"(hi) : "f"(x));
    float l = x - __uint_as_float(hi);
    asm("cvt.rna.tf32.f32 %0, %1;" : "=r"(lo) : "f"(l));
}

extern __shared__ float smem_dyn[];

// ===========================================================================
// rnn_kernel: PERSISTENT — one launch runs all 127 steps.
// EXACT R12 shape: 128 CTAs (1/SM), 256 threads, CTA tile 128x64,
// warp tile 32x32, NST=3, KCH=64, 16 chunks, lookahead 2, CTA-granular
// single-spin step barrier (one atomic + one poll loop per CTA per step).
// Micro-adds vs R12 (zero new barriers/polls):
//   * stage-2 B prefetched alongside stages 0/1 before the step barrier
//     (stage 2 dead after post-mainloop sync); ch=0 refill becomes A-only.
//   * g_len loads hoisted out of the t-loop (t-invariant).
// ===========================================================================
#define KCH        64
#define NCHK       (HDIM / KCH)            /* 16 */
#define PITCH      68                      /* 68 ≡ 4 (mod 32): conflict-free */
#define A_F        (128 * PITCH)           /* 8704 floats */
#define B_F        (64  * PITCH)           /* 4352 floats */
#define STAGE_F    (A_F + B_F)             /* 13056 floats = 52224 B */
#define NST        3
#define RNN_SMEM   (NST * STAGE_F * 4)     /* 156672 B */

__global__ void __launch_bounds__(256, 1)
rnn_kernel(const float* __restrict__ W_hh, const int* __restrict__ ids) {
    const int tid  = threadIdx.x;
    const int lane = tid & 31, warp = tid >> 5;
    const int wm = warp & 3, wn = warp >> 2;       // 4x2 warps, each 32x32
    const int g  = lane >> 2, c = lane & 3;
    const int grp = blockIdx.x >> 4;
    const int sub = blockIdx.x & 15;
    const int m0 = grp * 128;
    const int n0 = sub * 64;
    volatile unsigned* bar = &g_bar[grp];

    #define LOAD_A(st, k0, Hp)                                                     \
        do {                                                                       \
            float* base = smem_dyn + (st) * STAGE_F;                               \
            _Pragma("unroll")                                                      \
            for (int i = 0; i < 8; i++) {                                          \
                int j = tid + i * 256;                                             \
                int r = j >> 4, c16 = j & 15;                                      \
                cp16(base + r * PITCH + c16 * 4,                                   \
                     (Hp) + (size_t)(m0 + r) * HDIM + (k0) + c16 * 4);             \
            }                                                                      \
        } while (0)
    #define LOAD_B(st, k0)                                                         \
        do {                                                                       \
            float* base = smem_dyn + (st) * STAGE_F + A_F;                         \
            _Pragma("unroll")                                                      \
            for (int i = 0; i < 4; i++) {                                          \
                int j = tid + i * 256;                                             \
                int r = j >> 4, c16 = j & 15;                                      \
                cp16(base + r * PITCH + c16 * 4,                                   \
                     W_hh + (size_t)(n0 + r) * HDIM + (k0) + c16 * 4);             \
            }                                                                      \
        } while (0)

    #define LDFRAG(da, db, ksv)                                                    \
        do {                                                                       \
            _Pragma("unroll")                                                      \
            for (int mt = 0; mt < 2; mt++) {                                       \
                const float* ap = A + (mt * 16 + g) * PITCH + (ksv) * 8 + c;       \
                da[mt][0] = __float_as_uint(ap[0]);                                \
                da[mt][1] = __float_as_uint(ap[8 * PITCH]);                        \
                da[mt][2] = __float_as_uint(ap[4]);                                \
                da[mt][3] = __float_as_uint(ap[8 * PITCH + 4]);                    \
            }                                                                      \
            _Pragma("unroll")                                                      \
            for (int nt = 0; nt < 4; nt++) {                                       \
                const float* bp = B + (nt * 8 + g) * PITCH + (ksv) * 8 + c;        \
                db[nt][0] = __float_as_uint(bp[0]);                                \
                db[nt][1] = __float_as_uint(bp[4]);                                \
            }                                                                      \
        } while (0)

    // ---- hoisted t-invariant epilogue scalars ------------------------------
    const int eR0 = m0 + wm * 32 + g;              // mt=0 rows: eR0, eR0+8
    const int eR1 = eR0 + 8;
    const int eR2 = eR0 + 16;                      // mt=1 rows: eR2, eR2+8
    const int eR3 = eR0 + 24;
    const int len0 = g_len[eR0], len1 = g_len[eR1];
    const int len2 = g_len[eR2], len3 = g_len[eR3];

    // W for stages 0/1/2 of the first step (uncommitted; joins first commit)
    LOAD_B(0, 0);
    LOAD_B(1, KCH);
    LOAD_B(2, 2 * KCH);

    for (int t = 1; t < SEQ; t++) {
        const float* __restrict__ Hprev = g_H + (size_t)(t - 1) * BATCH * HDIM;
        float* __restrict__ Hout        = g_H + (size_t)t       * BATCH * HDIM;

        float acc[2][4][4] = {};

        // prologue: B0/B1/B2 already prefetched; A0, A1 here
        LOAD_A(0, 0, Hprev);
        asm volatile("cp.async.commit_group;\n");   // G0 = {B0, B1, B2, A0}
        LOAD_A(1, KCH, Hprev);
        asm volatile("cp.async.commit_group;\n");   // G1 = {A1}

        for (int ch = 0; ch < NCHK; ch++) {
            if (ch < NCHK - 1) asm volatile("cp.async.wait_group 1;\n");
            else               asm volatile("cp.async.wait_group 0;\n");
            __syncthreads();

            const int st = ch % NST;
            const float* A = smem_dyn + st * STAGE_F + (wm * 32) * PITCH;
            const float* B = smem_dyn + st * STAGE_F + A_F + (wn * 32) * PITCH;

            uint32_t af[2][2][4], bf[2][4][2];
            LDFRAG(af[0], bf[0], 0);
            #pragma unroll
            for (int ks = 0; ks < KCH / 8; ks++) {
                const int cur = ks & 1;
                if (ks < KCH / 8 - 1) LDFRAG(af[cur ^ 1], bf[cur ^ 1], ks + 1);
                #pragma unroll
                for (int mt = 0; mt < 2; mt++)
                    #pragma unroll
                    for (int nt = 0; nt < 4; nt++)
                        mma_tf32(acc[mt][nt], af[cur][mt], bf[cur][nt]);
            }

            if (ch == 0) {
                // stage 2's B was prefetched pre-barrier: A-only refill
                LOAD_A(2, 2 * KCH, Hprev);
                asm volatile("cp.async.commit_group;\n");
            } else if (ch + 2 < NCHK) {
                const int st2 = (ch + 2) % NST;
                LOAD_A(st2, (ch + 2) * KCH, Hprev);
                LOAD_B(st2, (ch + 2) * KCH);
                asm volatile("cp.async.commit_group;\n");
            }
        }

        // all warps done with stages 0/1/2 before overwriting their B halves
        __syncthreads();
        if (t + 1 < SEQ) {        // next step's W prefetch (step-invariant)
            LOAD_B(0, 0);
            LOAD_B(1, KCH);
            LOAD_B(2, 2 * KCH);
        }

        // ---- epilogue: + Q gather, tanh, mask ------------------------------
        const int c2 = c * 2;
        #pragma unroll
        for (int mt = 0; mt < 2; mt++) {
            const int rA = (mt == 0) ? eR0 : eR2;
            const int rB = (mt == 0) ? eR1 : eR3;
            const int idA = ids[rA * SEQ + t];
            const int idB = ids[rB * SEQ + t];
            const bool mA = t < ((mt == 0) ? len0 : len2);
            const bool mB = t < ((mt == 0) ? len1 : len3);
            const float* q0 = g_Q + (size_t)idA * HDIM;
            const float* q1 = g_Q + (size_t)idB * HDIM;
            float* o0 = Hout + (size_t)rA * HDIM;
            float* o1 = Hout + (size_t)rB * HDIM;
            const float* p0 = Hprev + (size_t)rA * HDIM;
            const float* p1 = Hprev + (size_t)rB * HDIM;
            #pragma unroll
            for (int nt = 0; nt < 4; nt++) {
                const int n = n0 + wn * 32 + nt * 8 + c2;
                o0[n]     = mA ? tanhf(acc[mt][nt][0] + q0[n])     : p0[n];
                o0[n + 1] = mA ? tanhf(acc[mt][nt][1] + q0[n + 1]) : p0[n + 1];
                o1[n]     = mB ? tanhf(acc[mt][nt][2] + q1[n])     : p1[n];
                o1[n + 1] = mB ? tanhf(acc[mt][nt][3] + q1[n + 1]) : p1[n + 1];
            }
        }

        if (t + 1 >= SEQ) break;

        // ---- CTA-granular group barrier (R12 form: 16 atomics/step) --------
        __threadfence();                          // publish this thread's stores
        __syncthreads();                          // all threads fenced
        if (tid == 0) {
            atomicAdd((unsigned*)&g_bar[grp], 1u);
            const unsigned target = 16u * (unsigned)t;
            while (*bar < target) __nanosleep(32);
        }
        __syncthreads();
        __threadfence();                          // acquire before reading H[t]
    }
    #undef LOAD_A
    #undef LOAD_B
    #undef LDFRAG
}

// ===========================================================================
// y_kernel v3 (unchanged R12): tensor-core GEMM, hi/lo tf32 split.
// ===========================================================================
#define YKCH      64
#define YNCHK     (HDIM / YKCH)             /* 16 */
#define YPITCH    68
#define YA_F      (128 * YPITCH)            /* 8704 floats */
#define YB_F      (8   * YPITCH)            /* 544 floats */
#define YSTAGE_F  (YA_F + YB_F)             /* 9248 floats = 36992 B */
#define YNST      3
#define Y_SMEM    (YNST * YSTAGE_F * 4)     /* 110976 B */

__global__ void __launch_bounds__(128, 1)
y_kernel(const float* __restrict__ W_out,
         const float* __restrict__ b_out,
         float* __restrict__ y) {
    const int tid  = threadIdx.x;
    const int lane = tid & 31, warp = tid >> 5;
    const int g = lane >> 2, c = lane & 3;
    const int m0 = blockIdx.x * 128;        // row block (r = t*BATCH + b)

    #define YLOAD(st, k0)                                                          \
        do {                                                                       \
            float* base = smem_dyn + (st) * YSTAGE_F;                              \
            _Pragma("unroll")                                                      \
            for (int i = 0; i < 16; i++) {                                         \
                int j = tid + i * 128;                                             \
                int r = j >> 4, c16 = j & 15;                                      \
                cp16(base + r * YPITCH + c16 * 4,                                  \
                     g_H + (size_t)(m0 + r) * HDIM + (k0) + c16 * 4);              \
            }                                                                      \
            {                                                                      \
                int r = tid >> 4, c16 = tid & 15;                                  \
                cp16(base + YA_F + r * YPITCH + c16 * 4,                           \
                     W_out + (size_t)r * HDIM + (k0) + c16 * 4);                   \
            }                                                                      \
            asm volatile("cp.async.commit_group;\n");                              \
        } while (0)

    float acc[2][4] = {};

    YLOAD(0, 0);
    YLOAD(1, YKCH);

    for (int ch = 0; ch < YNCHK; ch++) {
        if (ch < YNCHK - 1) asm volatile("cp.async.wait_group 1;\n");
        else                asm volatile("cp.async.wait_group 0;\n");
        __syncthreads();

        const int st = ch % YNST;
        const float* A = smem_dyn + st * YSTAGE_F + (warp * 32) * YPITCH;
        const float* B = smem_dyn + st * YSTAGE_F + YA_F;

        #pragma unroll
        for (int ks = 0; ks < YKCH / 8; ks++) {
            uint32_t bh[2], bl[2];
            {
                const float* bp = B + g * YPITCH + ks * 8 + c;
                split_tf32(bp[0], bh[0], bl[0]);
                split_tf32(bp[4], bh[1], bl[1]);
            }
            #pragma unroll
            for (int mt = 0; mt < 2; mt++) {
                const float* ap = A + (mt * 16 + g) * YPITCH + ks * 8 + c;
                uint32_t ah[4], al[4];
                split_tf32(ap[0],            ah[0], al[0]);
                split_tf32(ap[8 * YPITCH],   ah[1], al[1]);
                split_tf32(ap[4],            ah[2], al[2]);
                split_tf32(ap[8 * YPITCH+4], ah[3], al[3]);
                mma_tf32(acc[mt], ah, bh);    // hi*hi
                mma_tf32(acc[mt], al, bh);    // lo*hi
                mma_tf32(acc[mt], ah, bl);    // hi*lo
            }
        }

        if (ch + 2 < YNCHK) YLOAD((ch + 2) % YNST, (ch + 2) * YKCH);
    }

    const int n0t = 2 * c;                          // tags 2c, 2c+1
    const float bo0 = b_out[n0t], bo1 = b_out[n0t + 1];
    #pragma unroll
    for (int mt = 0; mt < 2; mt++) {
        const int rA = m0 + warp * 32 + mt * 16 + g;
        const int rB = rA + 8;
        const int tA = rA >> 10, bA = rA & 1023;    // r = t*BATCH + b
        const int tB = rB >> 10, bB = rB & 1023;
        float2 vA = make_float2(acc[mt][0] + bo0, acc[mt][1] + bo1);
        float2 vB = make_float2(acc[mt][2] + bo0, acc[mt][3] + bo1);
        *(float2*)(y + ((size_t)bA * SEQ + tA) * NTAGS + n0t) = vA;
        *(float2*)(y + ((size_t)bB * SEQ + tB) * NTAGS + n0t) = vB;
    }
    #undef YLOAD
}

// ===========================================================================
extern "C" void kernel_launch(void* const* d_in, const int* in_sizes, int n_in,
                              void* d_out, int out_size) {
    (void)in_sizes; (void)n_in; (void)out_size;
    const int*   ids   = (const int*)  d_in[0];
    const float* emb   = (const float*)d_in[1];
    const float* W_ih  = (const float*)d_in[2];
    const float* W_hh  = (const float*)d_in[3];
    const float* b_ih  = (const float*)d_in[4];
    const float* b_hh  = (const float*)d_in[5];
    const float* W_out = (const float*)d_in[6];
    const float* b_out = (const float*)d_in[7];
    float* y = (float*)d_out;

    cudaFuncSetAttribute(rnn_kernel,
                         cudaFuncAttributeMaxDynamicSharedMemorySize, RNN_SMEM);
    cudaFuncSetAttribute(y_kernel,
                         cudaFuncAttributeMaxDynamicSharedMemorySize, Y_SMEM);

    q_kernel<<<VOCAB, 256>>>(emb, W_ih, b_ih, b_hh);
    t0_kernel<<<BATCH, 128>>>(ids);
    rnn_kernel<<<128, 256, RNN_SMEM>>>(W_hh, ids);   // persistent: all 127 steps
    y_kernel<<<(BATCH * SEQ) / 128, 128, Y_SMEM>>>(W_out, b_out, y);
}